// round 3
// baseline (speedup 1.0000x reference)
#include <cuda_runtime.h>

// DegreePrediction: y[u] = sum_{s,t,v} (x*W_t)[s,t] * (W_r*r_zeros + r_const)[s,t,u,v]
// N = 80. Pure HBM-streaming reduction over three 80^4 fp32 tensors (491.5 MB).
//
// R3 change vs R2: block granularity 4x smaller (1 slice per block, 6400 blocks)
// to kill the end-of-kernel drain tail: with 4 slices/block only ~2.2
// block-generations fit per SM, and the final partial generation left DRAM
// starved for tens of us (DRAM active only ~70% despite saturation mid-run).
//
// Layout facts used:
//   - slice (s,t) is 6400 contiguous floats = 1600 float4
//   - u-row inside a slice is 80 contiguous floats = 20 float4
//   - with 320 threads, iteration j reads float4 index p = tid + 320*j,
//     fully coalesced across the block, and each thread's float4 stays inside
//     a single u-row: u = tid/20 + 16*j (constant per thread/j).

#define NN 80
#define SLICE_FLOATS (NN * NN)      // 6400
#define THREADS 320
#define J_ITERS 5                   // 1600 float4 / 320 threads
#define NUM_BLOCKS (NN * NN)        // 6400 blocks, 1 slice each

__global__ void zero_out_kernel(float* __restrict__ out) {
    int i = threadIdx.x;
    if (i < NN) out[i] = 0.0f;
}

__global__ __launch_bounds__(THREADS, 6)
void degree_pred_kernel(const float* __restrict__ x,
                        const float* __restrict__ r_zeros,
                        const float* __restrict__ r_const,
                        const float* __restrict__ weights_t,
                        const float* __restrict__ weights_r,
                        float* __restrict__ out)
{
    __shared__ float y_sh[NN];
    const int tid = threadIdx.x;
    if (tid < NN) y_sh[tid] = 0.0f;

    const int st = blockIdx.x;
    const float a = __ldg(&x[st]) * __ldg(&weights_t[st]);
    const size_t base = (size_t)st * SLICE_FLOATS;
    const float4* __restrict__ rz = reinterpret_cast<const float4*>(r_zeros   + base);
    const float4* __restrict__ rc = reinterpret_cast<const float4*>(r_const   + base);
    const float4* __restrict__ wr = reinterpret_cast<const float4*>(weights_r + base);

    // one scalar accumulator per j (fixed u per (thread, j))
    float acc[J_ITERS];

#pragma unroll
    for (int j = 0; j < J_ITERS; j++) {
        const int p = tid + THREADS * j;
        const float4 z = __ldcs(&rz[p]);
        const float4 c = __ldcs(&rc[p]);
        const float4 w = __ldcs(&wr[p]);
        float t = (c.x + c.y) + (c.z + c.w);
        t = fmaf(w.x, z.x, t);
        t = fmaf(w.y, z.y, t);
        t = fmaf(w.z, z.z, t);
        t = fmaf(w.w, z.w, t);
        acc[j] = a * t;
    }

    __syncthreads();

    const int u0 = tid / 20;   // 20 float4 per u-row
#pragma unroll
    for (int j = 0; j < J_ITERS; j++) {
        atomicAdd(&y_sh[u0 + 16 * j], acc[j]);
    }

    __syncthreads();
    if (tid < NN) atomicAdd(&out[tid], y_sh[tid]);
}

extern "C" void kernel_launch(void* const* d_in, const int* in_sizes, int n_in,
                              void* d_out, int out_size)
{
    const float* x         = (const float*)d_in[0];
    const float* r_zeros   = (const float*)d_in[1];
    const float* r_const   = (const float*)d_in[2];
    const float* weights_t = (const float*)d_in[3];
    const float* weights_r = (const float*)d_in[4];
    float* out = (float*)d_out;

    zero_out_kernel<<<1, 128>>>(out);
    degree_pred_kernel<<<NUM_BLOCKS, THREADS>>>(x, r_zeros, r_const,
                                                weights_t, weights_r, out);
}

// round 4
// speedup vs baseline: 1.3583x; 1.3583x over previous
#include <cuda_runtime.h>

// DegreePrediction: y[u] = sum_{s,t,v} (x*W_t)[s,t] * (W_r*r_zeros + r_const)[s,t,u,v]
// N = 80. Pure HBM-streaming reduction over three 80^4 fp32 tensors (491.5 MB).
//
// R4: back to R2 geometry (4 slices/block, 1600 blocks, 320 threads) + explicit
// register double-buffering across a flattened 20-iteration loop, so every warp
// always has >= 2 triples (6 LDG.128, 24 sectors) in flight regardless of how
// ptxas schedules under the register cap. Targets the latency-exposed regime
// (R1 and R2 both stuck at 5.5 TB/s with occupancy x2 apart).
//
// Layout facts:
//   - slice (s,t) = 6400 contiguous floats = 1600 float4
//   - u-row = 80 floats = 20 float4
//   - iteration j reads float4 p = tid + 320*j: coalesced, and each thread's
//     float4 stays in one u-row: u = tid/20 + 16*j.

#define NN 80
#define SLICE_FLOATS (NN * NN)      // 6400
#define THREADS 320
#define J_ITERS 5
#define K_SLICES 4
#define NUM_BLOCKS ((NN * NN) / K_SLICES)   // 1600

__global__ void zero_out_kernel(float* __restrict__ out) {
    int i = threadIdx.x;
    if (i < NN) out[i] = 0.0f;
}

__global__ __launch_bounds__(THREADS, 4)
void degree_pred_kernel(const float* __restrict__ x,
                        const float* __restrict__ r_zeros,
                        const float* __restrict__ r_const,
                        const float* __restrict__ weights_t,
                        const float* __restrict__ weights_r,
                        float* __restrict__ out)
{
    __shared__ float y_sh[NN];
    const int tid = threadIdx.x;
    if (tid < NN) y_sh[tid] = 0.0f;

    const int st0 = blockIdx.x * K_SLICES;

    // per-slice scalars, hoisted
    float a[K_SLICES];
#pragma unroll
    for (int k = 0; k < K_SLICES; k++)
        a[k] = __ldg(&x[st0 + k]) * __ldg(&weights_t[st0 + k]);

    float acc[J_ITERS];
#pragma unroll
    for (int j = 0; j < J_ITERS; j++) acc[j] = 0.0f;

    const size_t base0 = (size_t)st0 * SLICE_FLOATS;
    const float4* __restrict__ rz0 = reinterpret_cast<const float4*>(r_zeros   + base0);
    const float4* __restrict__ rc0 = reinterpret_cast<const float4*>(r_const   + base0);
    const float4* __restrict__ wr0 = reinterpret_cast<const float4*>(weights_r + base0);

    const int QPS = SLICE_FLOATS / 4;   // 1600 float4 per slice

    // ---- software pipeline: prefetch iteration it+1 while computing it ----
    float4 z0 = __ldcs(&rz0[tid]);
    float4 c0 = __ldcs(&rc0[tid]);
    float4 w0 = __ldcs(&wr0[tid]);

#pragma unroll
    for (int it = 0; it < K_SLICES * J_ITERS; it++) {
        const int k = it / J_ITERS;
        const int j = it % J_ITERS;

        float4 z1, c1, w1;
        if (it < K_SLICES * J_ITERS - 1) {
            const int itn = it + 1;
            const int pn = tid + THREADS * (itn % J_ITERS) + QPS * (itn / J_ITERS);
            z1 = __ldcs(&rz0[pn]);
            c1 = __ldcs(&rc0[pn]);
            w1 = __ldcs(&wr0[pn]);
        }

        float t = (c0.x + c0.y) + (c0.z + c0.w);
        t = fmaf(w0.x, z0.x, t);
        t = fmaf(w0.y, z0.y, t);
        t = fmaf(w0.z, z0.z, t);
        t = fmaf(w0.w, z0.w, t);
        acc[j] = fmaf(a[k], t, acc[j]);

        z0 = z1; c0 = c1; w0 = w1;
    }

    __syncthreads();

    const int u0 = tid / 20;   // 20 float4 per u-row
#pragma unroll
    for (int j = 0; j < J_ITERS; j++) {
        atomicAdd(&y_sh[u0 + 16 * j], acc[j]);
    }

    __syncthreads();
    if (tid < NN) atomicAdd(&out[tid], y_sh[tid]);
}

extern "C" void kernel_launch(void* const* d_in, const int* in_sizes, int n_in,
                              void* d_out, int out_size)
{
    const float* x         = (const float*)d_in[0];
    const float* r_zeros   = (const float*)d_in[1];
    const float* r_const   = (const float*)d_in[2];
    const float* weights_t = (const float*)d_in[3];
    const float* weights_r = (const float*)d_in[4];
    float* out = (float*)d_out;

    zero_out_kernel<<<1, 128>>>(out);
    degree_pred_kernel<<<NUM_BLOCKS, THREADS>>>(x, r_zeros, r_const,
                                                weights_t, weights_r, out);
}